// round 2
// baseline (speedup 1.0000x reference)
#include <cuda_runtime.h>
#include <math.h>

// Problem dims (fixed by metadata): E = B*N*K = 32768
#define E_MAX 32768

// Scratch (device globals: allocation-free per harness rules)
__device__ float g_h[E_MAX * 64];     // radial MLP hidden (post 2nd GELU)
__device__ float g_tmp[E_MAX * 288];  // feats@basis, laid out [e][j=i*3+f][m]

__device__ __forceinline__ float gelu_exact(float v) {
    return 0.5f * v * (1.0f + erff(v * 0.70710678118654752440f));
}

// ---------------------------------------------------------------------------
// Kernel 1: one warp per edge. MLP (Linear->LN->GELU)x2  +  tmp = feats@basis
// ---------------------------------------------------------------------------
__global__ __launch_bounds__(256)
void mlp_tmp_kernel(const float* __restrict__ edges,
                    const float* __restrict__ feats,
                    const float* __restrict__ basis,
                    const float* __restrict__ W1, const float* __restrict__ b1,
                    const float* __restrict__ g1, const float* __restrict__ beta1,
                    const float* __restrict__ W2, const float* __restrict__ b2,
                    const float* __restrict__ g2, const float* __restrict__ beta2,
                    int E)
{
    __shared__ float W1s[32 * 64];
    __shared__ float W2s[64 * 64];
    int tid = threadIdx.x;
    for (int i = tid; i < 32 * 64; i += blockDim.x) W1s[i] = W1[i];
    for (int i = tid; i < 64 * 64; i += blockDim.x) W2s[i] = W2[i];
    __syncthreads();

    int warp = tid >> 5, lane = tid & 31;
    int e = blockIdx.x * 8 + warp;
    if (e >= E) return;

    const unsigned FULL = 0xffffffffu;

    // x @ W1 + b1  (each lane owns output cols lane and lane+32)
    float xv = edges[(size_t)e * 32 + lane];
    float t0 = b1[lane], t1 = b1[lane + 32];
    #pragma unroll
    for (int k = 0; k < 32; k++) {
        float xk = __shfl_sync(FULL, xv, k);
        t0 = fmaf(xk, W1s[k * 64 + lane], t0);
        t1 = fmaf(xk, W1s[k * 64 + lane + 32], t1);
    }
    // LayerNorm over 64 (population var) + GELU
    float s = t0 + t1, sq = t0 * t0 + t1 * t1;
    #pragma unroll
    for (int o = 16; o > 0; o >>= 1) {
        s  += __shfl_xor_sync(FULL, s, o);
        sq += __shfl_xor_sync(FULL, sq, o);
    }
    float mean = s * (1.0f / 64.0f);
    float var  = sq * (1.0f / 64.0f) - mean * mean;
    float rstd = rsqrtf(var + 1e-5f);
    float h0 = gelu_exact((t0 - mean) * rstd * g1[lane]      + beta1[lane]);
    float h1 = gelu_exact((t1 - mean) * rstd * g1[lane + 32] + beta1[lane + 32]);

    // h1 @ W2 + b2
    t0 = b2[lane]; t1 = b2[lane + 32];
    #pragma unroll
    for (int k = 0; k < 32; k++) {
        float a = __shfl_sync(FULL, h0, k);   // h[k]
        float b = __shfl_sync(FULL, h1, k);   // h[k+32]
        t0 = fmaf(a, W2s[k * 64 + lane],            t0);
        t0 = fmaf(b, W2s[(k + 32) * 64 + lane],     t0);
        t1 = fmaf(a, W2s[k * 64 + lane + 32],       t1);
        t1 = fmaf(b, W2s[(k + 32) * 64 + lane + 32], t1);
    }
    s = t0 + t1; sq = t0 * t0 + t1 * t1;
    #pragma unroll
    for (int o = 16; o > 0; o >>= 1) {
        s  += __shfl_xor_sync(FULL, s, o);
        sq += __shfl_xor_sync(FULL, sq, o);
    }
    mean = s * (1.0f / 64.0f);
    var  = sq * (1.0f / 64.0f) - mean * mean;
    rstd = rsqrtf(var + 1e-5f);
    float o0 = gelu_exact((t0 - mean) * rstd * g2[lane]      + beta2[lane]);
    float o1 = gelu_exact((t1 - mean) * rstd * g2[lane + 32] + beta2[lane + 32]);
    g_h[(size_t)e * 64 + lane]      = o0;
    g_h[(size_t)e * 64 + lane + 32] = o1;

    // tmp[e][i*3+f][m] = sum_k feats[e,i,k] * basis[e,k,f*3+m]
    // lane = channel i; linear index i*9 + q with q = f*3+m
    const float* fp = feats + (size_t)e * 96 + lane * 3;
    float f0 = fp[0], f1 = fp[1], f2 = fp[2];
    const float* bp = basis + (size_t)e * 27;
    #pragma unroll
    for (int q = 0; q < 9; q++) {
        float v = f0 * bp[q] + f1 * bp[9 + q] + f2 * bp[18 + q];
        g_tmp[(size_t)e * 288 + lane * 9 + q] = v;
    }
}

// ---------------------------------------------------------------------------
// Kernel 2: fused (h @ W3-slab) -> rw tile in smem -> contract with tmp -> out
// CTA: 32 edges x 4 out-channels (384 W3 columns). 384 threads.
// ---------------------------------------------------------------------------
#define ETILE 32
#define K2_THREADS 384
// smem float offsets (padded strides to avoid bank conflicts in contraction)
#define WS_OFF   0            // [64][384]
#define HS_OFF   24576        // [32][64]
#define TMPS_OFF 26624        // [32][292] (288 used, pad 4)
#define RWS_OFF  35968        // [32][388] (384 used, pad 4)
#define SM2_FLOATS 48384
#define TMPS_STRIDE 292
#define RWS_STRIDE 388

__global__ __launch_bounds__(K2_THREADS)
void fused_rw_kernel(const float* __restrict__ W3, float* __restrict__ out, int E)
{
    extern __shared__ float sm2[];
    float* Ws   = sm2 + WS_OFF;
    float* hs   = sm2 + HS_OFF;
    float* tmps = sm2 + TMPS_OFF;
    float* rws  = sm2 + RWS_OFF;

    int tid = threadIdx.x;
    int e0 = blockIdx.x * ETILE;
    int colbase = blockIdx.y * 384;   // = o_base * 96 with o_base = 4*blockIdx.y

    // ---- load tiles ----
    for (int i = tid; i < ETILE * 64; i += K2_THREADS)
        hs[i] = g_h[(size_t)e0 * 64 + i];
    for (int i = tid; i < ETILE * 288; i += K2_THREADS) {
        int el = i / 288, r = i - el * 288;
        tmps[el * TMPS_STRIDE + r] = g_tmp[(size_t)e0 * 288 + i];
    }
    {
        const float4* W3v = (const float4*)W3;
        float4* Wsv = (float4*)Ws;
        int cb4 = colbase >> 2;
        for (int i = tid; i < 64 * 96; i += K2_THREADS) {
            int c = i / 96, v = i - c * 96;
            Wsv[c * 96 + v] = W3v[(size_t)c * 768 + cb4 + v];
        }
    }
    __syncthreads();

    // ---- GEMM: rw[32e][384c] = h[32][64] @ Ws[64][384] ----
    // thread tile: 4 edges x 8 cols
    int cg = tid % 48;   // col group: cols cg*8 .. cg*8+7
    int eg = tid / 48;   // edge group: edges eg*4 .. eg*4+3
    float acc[4][8];
    #pragma unroll
    for (int i = 0; i < 4; i++)
        #pragma unroll
        for (int j = 0; j < 8; j++) acc[i][j] = 0.0f;

    #pragma unroll 4
    for (int c = 0; c < 64; c++) {
        const float4* wr = (const float4*)(Ws + c * 384);
        float4 w0 = wr[cg * 2];
        float4 w1 = wr[cg * 2 + 1];
        #pragma unroll
        for (int i = 0; i < 4; i++) {
            float hv = hs[(eg * 4 + i) * 64 + c];   // broadcast within warp
            acc[i][0] = fmaf(hv, w0.x, acc[i][0]);
            acc[i][1] = fmaf(hv, w0.y, acc[i][1]);
            acc[i][2] = fmaf(hv, w0.z, acc[i][2]);
            acc[i][3] = fmaf(hv, w0.w, acc[i][3]);
            acc[i][4] = fmaf(hv, w1.x, acc[i][4]);
            acc[i][5] = fmaf(hv, w1.y, acc[i][5]);
            acc[i][6] = fmaf(hv, w1.z, acc[i][6]);
            acc[i][7] = fmaf(hv, w1.w, acc[i][7]);
        }
    }
    #pragma unroll
    for (int i = 0; i < 4; i++) {
        float4* r = (float4*)(rws + (eg * 4 + i) * RWS_STRIDE + cg * 8);
        r[0] = make_float4(acc[i][0], acc[i][1], acc[i][2], acc[i][3]);
        r[1] = make_float4(acc[i][4], acc[i][5], acc[i][6], acc[i][7]);
    }
    __syncthreads();

    // ---- contract: out[e, o, m] = sum_j rw[e][oo*96+j] * tmp[e][j][m] ----
    // 384 threads = 32 edges x 4 oo x 3 m
    int m  = tid % 3;
    int p  = tid / 3;        // 0..127
    int el = p & 31;
    int oo = p >> 5;         // 0..3
    const float* rp = rws  + el * RWS_STRIDE  + oo * 96;
    const float* tp = tmps + el * TMPS_STRIDE + m;
    float a = 0.0f;
    #pragma unroll 8
    for (int j = 0; j < 96; j++)
        a = fmaf(rp[j], tp[j * 3], a);

    int e = e0 + el;
    if (e < E)
        out[(size_t)e * 96 + (blockIdx.y * 4 + oo) * 3 + m] = a;
}

// ---------------------------------------------------------------------------
extern "C" void kernel_launch(void* const* d_in, const int* in_sizes, int n_in,
                              void* d_out, int out_size)
{
    const float* edges = (const float*)d_in[0];
    const float* feats = (const float*)d_in[1];
    const float* basis = (const float*)d_in[2];
    const float* W1    = (const float*)d_in[3];
    const float* b1    = (const float*)d_in[4];
    const float* g1    = (const float*)d_in[5];
    const float* beta1 = (const float*)d_in[6];
    const float* W2    = (const float*)d_in[7];
    const float* b2    = (const float*)d_in[8];
    const float* g2    = (const float*)d_in[9];
    const float* beta2 = (const float*)d_in[10];
    const float* W3    = (const float*)d_in[11];
    float* out = (float*)d_out;

    int E = in_sizes[0] / 32;   // edges is (E, 32)
    if (E > E_MAX) E = E_MAX;

    mlp_tmp_kernel<<<(E + 7) / 8, 256>>>(edges, feats, basis,
                                         W1, b1, g1, beta1,
                                         W2, b2, g2, beta2, E);

    const int smem_bytes = SM2_FLOATS * (int)sizeof(float);  // 193536
    cudaFuncSetAttribute(fused_rw_kernel,
                         cudaFuncAttributeMaxDynamicSharedMemorySize, smem_bytes);
    dim3 grid((E + ETILE - 1) / ETILE, 8);   // 8 o-groups of 4 channels
    fused_rw_kernel<<<grid, K2_THREADS, smem_bytes>>>(W3, out, E);
}

// round 4
// speedup vs baseline: 1.8888x; 1.8888x over previous
#include <cuda_runtime.h>
#include <math.h>

// Problem dims (fixed by metadata): E = B*N*K = 32768
#define E_MAX 32768

// Scratch (device globals: allocation-free per harness rules)
// g_h is stored TRANSPOSED: [c][e] so kernel2 can cp.async contiguous 32-edge rows
__device__ float g_h[64 * E_MAX];
__device__ float g_tmp[E_MAX * 288];  // feats@basis, [e][j=i*3+f][m]

__device__ __forceinline__ float gelu_exact(float v) {
    return 0.5f * v * (1.0f + erff(v * 0.70710678118654752440f));
}

// ---- f32x2 packed-FMA helpers (sm_103a FFMA2) -----------------------------
typedef unsigned long long ull;

__device__ __forceinline__ ull dup2(float v) {
    union { float2 f2; ull u; } c;
    c.f2 = make_float2(v, v);
    return c.u;
}
#define FMA2(acc, a, b) \
    asm("fma.rn.f32x2 %0, %1, %2, %0;" : "+l"(acc) : "l"(a), "l"(b))

// ---- cp.async helpers -----------------------------------------------------
__device__ __forceinline__ void cp16(void* sdst, const void* gsrc) {
    unsigned s = (unsigned)__cvta_generic_to_shared(sdst);
    asm volatile("cp.async.cg.shared.global [%0], [%1], 16;" :: "r"(s), "l"(gsrc));
}
__device__ __forceinline__ void cp_commit() {
    asm volatile("cp.async.commit_group;");
}
template <int N>
__device__ __forceinline__ void cp_wait() {
    asm volatile("cp.async.wait_group %0;" :: "n"(N));
}

// ---------------------------------------------------------------------------
// Kernel 1: one warp per edge. MLP (Linear->LN->GELU)x2  +  tmp = feats@basis
// ---------------------------------------------------------------------------
__global__ __launch_bounds__(256)
void mlp_tmp_kernel(const float* __restrict__ edges,
                    const float* __restrict__ feats,
                    const float* __restrict__ basis,
                    const float* __restrict__ W1, const float* __restrict__ b1,
                    const float* __restrict__ g1, const float* __restrict__ beta1,
                    const float* __restrict__ W2, const float* __restrict__ b2,
                    const float* __restrict__ g2, const float* __restrict__ beta2,
                    int E)
{
    __shared__ float W1s[32 * 64];
    __shared__ float W2s[64 * 64];
    int tid = threadIdx.x;
    for (int i = tid; i < 32 * 64; i += blockDim.x) W1s[i] = W1[i];
    for (int i = tid; i < 64 * 64; i += blockDim.x) W2s[i] = W2[i];
    __syncthreads();

    int warp = tid >> 5, lane = tid & 31;
    int e = blockIdx.x * 8 + warp;
    if (e >= E) return;

    const unsigned FULL = 0xffffffffu;

    float xv = edges[(size_t)e * 32 + lane];
    float t0 = b1[lane], t1 = b1[lane + 32];
    #pragma unroll
    for (int k = 0; k < 32; k++) {
        float xk = __shfl_sync(FULL, xv, k);
        t0 = fmaf(xk, W1s[k * 64 + lane], t0);
        t1 = fmaf(xk, W1s[k * 64 + lane + 32], t1);
    }
    float s = t0 + t1, sq = t0 * t0 + t1 * t1;
    #pragma unroll
    for (int o = 16; o > 0; o >>= 1) {
        s  += __shfl_xor_sync(FULL, s, o);
        sq += __shfl_xor_sync(FULL, sq, o);
    }
    float mean = s * (1.0f / 64.0f);
    float var  = sq * (1.0f / 64.0f) - mean * mean;
    float rstd = rsqrtf(var + 1e-5f);
    float h0 = gelu_exact((t0 - mean) * rstd * g1[lane]      + beta1[lane]);
    float h1 = gelu_exact((t1 - mean) * rstd * g1[lane + 32] + beta1[lane + 32]);

    t0 = b2[lane]; t1 = b2[lane + 32];
    #pragma unroll
    for (int k = 0; k < 32; k++) {
        float a = __shfl_sync(FULL, h0, k);
        float b = __shfl_sync(FULL, h1, k);
        t0 = fmaf(a, W2s[k * 64 + lane],             t0);
        t0 = fmaf(b, W2s[(k + 32) * 64 + lane],      t0);
        t1 = fmaf(a, W2s[k * 64 + lane + 32],        t1);
        t1 = fmaf(b, W2s[(k + 32) * 64 + lane + 32], t1);
    }
    s = t0 + t1; sq = t0 * t0 + t1 * t1;
    #pragma unroll
    for (int o = 16; o > 0; o >>= 1) {
        s  += __shfl_xor_sync(FULL, s, o);
        sq += __shfl_xor_sync(FULL, sq, o);
    }
    mean = s * (1.0f / 64.0f);
    var  = sq * (1.0f / 64.0f) - mean * mean;
    rstd = rsqrtf(var + 1e-5f);
    float o0 = gelu_exact((t0 - mean) * rstd * g2[lane]      + beta2[lane]);
    float o1 = gelu_exact((t1 - mean) * rstd * g2[lane + 32] + beta2[lane + 32]);
    // transposed store: g_h[c][e]
    g_h[(size_t)lane * E_MAX + e]        = o0;
    g_h[(size_t)(lane + 32) * E_MAX + e] = o1;

    // tmp[e][i*3+f][m] = sum_k feats[e,i,k] * basis[e,k,f*3+m]
    const float* fp = feats + (size_t)e * 96 + lane * 3;
    float f0 = fp[0], f1 = fp[1], f2 = fp[2];
    const float* bp = basis + (size_t)e * 27;
    #pragma unroll
    for (int q = 0; q < 9; q++) {
        float v = f0 * bp[q] + f1 * bp[9 + q] + f2 * bp[18 + q];
        g_tmp[(size_t)e * 288 + lane * 9 + q] = v;
    }
}

// ---------------------------------------------------------------------------
// Kernel 2: persistent slab CTAs.
// CTA = 1 slab of 384 W3 columns (4 output channels), loops over 32-edge tiles.
// 384 threads: GEMM thread-tile = 4 edges x 8 cols (split {4cg, 192+4cg}),
// f32x2 packed FMA along column pairs.
// ---------------------------------------------------------------------------
#define ETILE 32
#define K2_THREADS 384
#define NE_CTAS 18
// smem float offsets
#define WS_OFF    0            // [64][384]
#define HS_OFF    24576        // [2][64][32] double-buffered
#define TMPS_OFF  28672        // [32][292]
#define RWS_OFF   38016        // [32][388]
#define SM2_FLOATS 50432       // 201,728 bytes
#define TMPS_STRIDE 292
#define RWS_STRIDE  388

__global__ __launch_bounds__(K2_THREADS, 1)
void fused_rw_kernel(const float* __restrict__ W3, float* __restrict__ out, int E)
{
    extern __shared__ float sm2[];
    float* Ws   = sm2 + WS_OFF;
    float* hsA  = sm2 + HS_OFF;          // two buffers of 2048 floats
    float* tmps = sm2 + TMPS_OFF;
    float* rws  = sm2 + RWS_OFF;

    const int tid = threadIdx.x;
    const int slab = blockIdx.y;          // 0..7, covers cols slab*384..+383
    const int colbase = slab * 384;
    const int tiles = (E + ETILE - 1) / ETILE;

    // GEMM mapping
    const int cg  = tid % 48;             // cols {4cg..4cg+3} and {192+4cg..}
    const int eg  = tid / 48;             // edges eg*4..eg*4+3
    const int cg4 = cg * 4;
    const int e4  = eg * 4;
    // contraction mapping
    const int m  = tid % 3;
    const int p  = tid / 3;
    const int el = p & 31;
    const int oo = p >> 5;                // 0..3

    // ---- prologue: async-load W slab + first h tile ----
    for (int q = tid; q < 64 * 96; q += K2_THREADS) {
        int c = q / 96, v = (q - c * 96) * 4;
        cp16(Ws + c * 384 + v, W3 + (size_t)c * 3072 + colbase + v);
    }
    {
        int t0 = blockIdx.x;
        if (t0 < tiles) {
            int e0 = t0 * ETILE;
            for (int q = tid; q < 64 * 8; q += K2_THREADS) {
                int c = q >> 3, v = (q & 7) * 4;
                cp16(hsA + c * 32 + v, g_h + (size_t)c * E_MAX + e0 + v);
            }
        }
    }
    cp_commit();

    bool first = true;
    int par = 0;

    for (int tt = blockIdx.x; tt < tiles; tt += NE_CTAS) {
        int e0 = tt * ETILE;

        if (first) {
            cp_wait<0>();
            __syncthreads();
            first = false;
        }

        // ---- issue tmps(tt) : group T ----
        for (int q = tid; q < 32 * 72; q += K2_THREADS) {
            int r = q / 72, v = (q - r * 72) * 4;
            cp16(tmps + r * TMPS_STRIDE + v, g_tmp + (size_t)(e0 + r) * 288 + v);
        }
        cp_commit();

        // ---- issue hs(tt + NE) into other buffer : group H ----
        {
            int tn = tt + NE_CTAS;
            if (tn < tiles) {
                int en = tn * ETILE;
                float* hd = hsA + ((par ^ 1) << 11);
                for (int q = tid; q < 64 * 8; q += K2_THREADS) {
                    int c = q >> 3, v = (q & 7) * 4;
                    cp16(hd + c * 32 + v, g_h + (size_t)c * E_MAX + en + v);
                }
            }
            cp_commit();   // commit even if empty to keep group accounting
        }

        // ---- GEMM: rw[32e][384c] = h[32][64] @ Ws[64][384], f32x2 packed ----
        const float* hsb = hsA + (par << 11);
        ull acc[4][4];
        #pragma unroll
        for (int i = 0; i < 4; i++)
            #pragma unroll
            for (int j = 0; j < 4; j++) acc[i][j] = 0ull;

        #pragma unroll 8
        for (int c = 0; c < 64; c++) {
            ulonglong2 wa = *(const ulonglong2*)(Ws + c * 384 + cg4);
            ulonglong2 wb = *(const ulonglong2*)(Ws + c * 384 + 192 + cg4);
            ull h2[4];
            #pragma unroll
            for (int i = 0; i < 4; i++) h2[i] = dup2(hsb[c * 32 + e4 + i]);
            #pragma unroll
            for (int i = 0; i < 4; i++) {
                FMA2(acc[i][0], h2[i], wa.x);
                FMA2(acc[i][1], h2[i], wa.y);
                FMA2(acc[i][2], h2[i], wb.x);
                FMA2(acc[i][3], h2[i], wb.y);
            }
        }

        cp_wait<1>();   // tmps(tt) landed (H may still be in flight)

        #pragma unroll
        for (int i = 0; i < 4; i++) {
            float* row = rws + (e4 + i) * RWS_STRIDE;
            *(ulonglong2*)(row + cg4)       = make_ulonglong2(acc[i][0], acc[i][1]);
            *(ulonglong2*)(row + 192 + cg4) = make_ulonglong2(acc[i][2], acc[i][3]);
        }
        __syncthreads();   // rws + tmps visible to all

        // ---- contraction: out[e,o,m] = sum_j rw[e][oo*96+j] * tmp[e][j][m] ----
        {
            const float* rp = rws  + el * RWS_STRIDE  + oo * 96;
            const float* tp = tmps + el * TMPS_STRIDE + m;
            float a = 0.0f;
            #pragma unroll
            for (int j4 = 0; j4 < 24; j4++) {
                float4 r4 = *(const float4*)(rp + j4 * 4);
                a = fmaf(r4.x, tp[(j4 * 4 + 0) * 3], a);
                a = fmaf(r4.y, tp[(j4 * 4 + 1) * 3], a);
                a = fmaf(r4.z, tp[(j4 * 4 + 2) * 3], a);
                a = fmaf(r4.w, tp[(j4 * 4 + 3) * 3], a);
            }
            int e = e0 + el;
            if (e < E)
                out[(size_t)e * 96 + (slab * 4 + oo) * 3 + m] = a;
        }

        cp_wait<0>();      // next h tile landed
        __syncthreads();   // everyone done reading tmps/rws before overwrite
        par ^= 1;
    }
}

// ---------------------------------------------------------------------------
extern "C" void kernel_launch(void* const* d_in, const int* in_sizes, int n_in,
                              void* d_out, int out_size)
{
    const float* edges = (const float*)d_in[0];
    const float* feats = (const float*)d_in[1];
    const float* basis = (const float*)d_in[2];
    const float* W1    = (const float*)d_in[3];
    const float* b1    = (const float*)d_in[4];
    const float* g1    = (const float*)d_in[5];
    const float* beta1 = (const float*)d_in[6];
    const float* W2    = (const float*)d_in[7];
    const float* b2    = (const float*)d_in[8];
    const float* g2    = (const float*)d_in[9];
    const float* beta2 = (const float*)d_in[10];
    const float* W3    = (const float*)d_in[11];
    float* out = (float*)d_out;

    int E = in_sizes[0] / 32;
    if (E > E_MAX) E = E_MAX;

    mlp_tmp_kernel<<<(E + 7) / 8, 256>>>(edges, feats, basis,
                                         W1, b1, g1, beta1,
                                         W2, b2, g2, beta2, E);

    static bool attr_set = false;
    const int smem_bytes = SM2_FLOATS * (int)sizeof(float);  // 201,728
    if (!attr_set) {
        cudaFuncSetAttribute(fused_rw_kernel,
                             cudaFuncAttributeMaxDynamicSharedMemorySize, smem_bytes);
        attr_set = true;
    }
    dim3 grid(NE_CTAS, 8);   // 144 persistent CTAs: 18 edge-stripes x 8 slabs
    fused_rw_kernel<<<grid, K2_THREADS, smem_bytes>>>(W3, out, E);
}